// round 1
// baseline (speedup 1.0000x reference)
#include <cuda_runtime.h>
#include <math.h>

// VectorQuantizer: x [65536, 64] f32, embeddings [64, 1024] f32.
// Outputs concatenated into f32 d_out:
//   [0 .. 4194303]  quantized_st (== quantized numerically)
//   [4194304]       loss = 1.25 * mean((q - x)^2)
//   [4194305]       perplexity
//   [4194306 .. +65535] encoding_indices (as float)

#define NROWS 65536
#define DD    64
#define KC    1024
#define BM    128
#define BN    128
#define NCH   (KC / BN)      // 8
#define ASTRIDE 68           // padded row stride for x tile in smem
#define NQ    (NROWS * DD)   // 4194304

// -------- device scratch (no allocations allowed) --------
__device__ float g_ET[KC * DD];     // embeddings transposed [K][D]
__device__ float g_enorm[KC];       // ||e_k||^2
__device__ int   g_counts[KC];      // histogram
__device__ float g_loss;            // sum of squared diffs

typedef unsigned long long u64;

__device__ __forceinline__ u64 pack_dup(float a) {
    u64 r;
    asm("mov.b64 %0, {%1, %1};" : "=l"(r) : "f"(a));
    return r;
}
__device__ __forceinline__ void fma2(u64 &d, u64 a, u64 b) {
    asm("fma.rn.f32x2 %0, %1, %2, %3;" : "=l"(d) : "l"(a), "l"(b), "l"(d));
}
__device__ __forceinline__ float2 unpack2(u64 v) {
    float2 f;
    asm("mov.b64 {%0, %1}, %2;" : "=f"(f.x), "=f"(f.y) : "l"(v));
    return f;
}

// -------- prep: e-norms, E^T, zero scratch --------
__global__ void vq_prep(const float* __restrict__ E) {
    int k = blockIdx.x * 256 + threadIdx.x;
    if (k < KC) {
        float s = 0.f;
        #pragma unroll
        for (int d = 0; d < DD; d++) {
            float v = E[d * KC + k];        // coalesced along k
            s = fmaf(v, v, s);
            g_ET[k * DD + d] = v;
        }
        g_enorm[k] = s;
        g_counts[k] = 0;
        if (k == 0) g_loss = 0.f;
    }
}

// -------- main: GEMM + argmin + gather + loss + histogram --------
extern __shared__ float sm[];

__global__ __launch_bounds__(256) void vq_main(const float* __restrict__ x,
                                               const float* __restrict__ E,
                                               float* __restrict__ out) {
    float* As      = sm;                       // BM*ASTRIDE = 8704 floats
    float* Bs      = sm + BM * ASTRIDE;        // 64*BN      = 8192 floats
    float* enorm_s = Bs + 64 * BN;             // BN
    float* xnorm_s = enorm_s + BN;             // BM
    int*   win     = (int*)(xnorm_s + BM);     // BM

    const int tid = threadIdx.x;
    const int tx = tid & 15;        // 16 code-groups of 8
    const int ty = tid >> 4;        // 16 row-groups of 8
    const int blockRow = blockIdx.x * BM;

    // ---- load x tile [BM x 64], row-major, padded ----
    const float* xg = x + (size_t)blockRow * DD;
    #pragma unroll
    for (int it = 0; it < 8; it++) {
        int g = tid + 256 * it;          // 2048 float4s
        int row = g >> 4, c4 = g & 15;
        float4 v = *reinterpret_cast<const float4*>(xg + row * DD + c4 * 4);
        *reinterpret_cast<float4*>(As + row * ASTRIDE + c4 * 4) = v;
    }
    __syncthreads();

    // ---- row norms ||x||^2 ----
    if (tid < BM) {
        const float* r = As + tid * ASTRIDE;
        float s = 0.f;
        #pragma unroll
        for (int d = 0; d < DD; d++) s = fmaf(r[d], r[d], s);
        xnorm_s[tid] = s;
    }

    float best[8];
    int   bidx[8];
    #pragma unroll
    for (int i = 0; i < 8; i++) { best[i] = 3.4e38f; bidx[i] = 0; }

    for (int ch = 0; ch < NCH; ch++) {
        __syncthreads();   // protect Bs from previous chunk's readers
        // load E chunk [64 x BN] (row d of E is contiguous: coalesced)
        #pragma unroll
        for (int it = 0; it < 8; it++) {
            int g = tid + 256 * it;     // 2048 float4s
            int d = g >> 5, c4 = g & 31;
            float4 v = *reinterpret_cast<const float4*>(E + d * KC + ch * BN + c4 * 4);
            *reinterpret_cast<float4*>(Bs + d * BN + c4 * 4) = v;
        }
        if (tid < BN) enorm_s[tid] = g_enorm[ch * BN + tid];
        __syncthreads();

        u64 acc[8][4];
        #pragma unroll
        for (int i = 0; i < 8; i++)
            #pragma unroll
            for (int j = 0; j < 4; j++) acc[i][j] = 0ULL;

        #pragma unroll 8
        for (int kk = 0; kk < DD; kk++) {
            const ulonglong2* bp =
                reinterpret_cast<const ulonglong2*>(Bs + kk * BN + tx * 8);
            ulonglong2 b01 = bp[0];
            ulonglong2 b23 = bp[1];
            #pragma unroll
            for (int i = 0; i < 8; i++) {
                u64 av = pack_dup(As[(ty * 8 + i) * ASTRIDE + kk]);
                fma2(acc[i][0], av, b01.x);
                fma2(acc[i][1], av, b01.y);
                fma2(acc[i][2], av, b23.x);
                fma2(acc[i][3], av, b23.y);
            }
        }

        // ---- distance + running argmin (ascending code order => first-min tie-break) ----
        #pragma unroll
        for (int i = 0; i < 8; i++) {
            float xn = xnorm_s[ty * 8 + i];
            #pragma unroll
            for (int j2 = 0; j2 < 4; j2++) {
                float2 dv = unpack2(acc[i][j2]);
                int cl = tx * 8 + j2 * 2;
                // replicate reference rounding: (xnorm - 2*dot) + enorm
                float d0 = (xn - 2.f * dv.x) + enorm_s[cl];
                float d1 = (xn - 2.f * dv.y) + enorm_s[cl + 1];
                int code0 = ch * BN + cl;
                if (d0 < best[i]) { best[i] = d0; bidx[i] = code0; }
                if (d1 < best[i]) { best[i] = d1; bidx[i] = code0 + 1; }
            }
        }
    }
    __syncthreads();

    // ---- cross-thread argmin reduction (reuse Bs region) ----
    float* redD = Bs;                       // BM*16 floats
    int*   redI = (int*)(Bs + BM * 16);     // BM*16 ints
    #pragma unroll
    for (int i = 0; i < 8; i++) {
        int r = ty * 8 + i;
        redD[r * 16 + tx] = best[i];
        redI[r * 16 + tx] = bidx[i];
    }
    __syncthreads();

    if (tid < BM) {
        float bd = redD[tid * 16];
        int   bi = redI[tid * 16];
        #pragma unroll
        for (int t = 1; t < 16; t++) {
            float d = redD[tid * 16 + t];
            int   ix = redI[tid * 16 + t];
            if (d < bd || (d == bd && ix < bi)) { bd = d; bi = ix; }
        }
        win[tid] = bi;
        atomicAdd(&g_counts[bi], 1);
        out[(size_t)NQ + 2 + blockRow + tid] = (float)bi;
    }
    __syncthreads();

    // ---- gather quantized rows + loss partial ----
    int r    = tid >> 1;
    int half = tid & 1;
    int idx  = win[r];
    const float* qrow = g_ET + idx * DD + half * 32;
    const float* xr   = As + r * ASTRIDE + half * 32;
    float* orow = out + ((size_t)(blockRow + r)) * DD + half * 32;
    float lsum = 0.f;
    #pragma unroll
    for (int c4 = 0; c4 < 8; c4++) {
        float4 q  = *reinterpret_cast<const float4*>(qrow + c4 * 4);
        float4 xv = *reinterpret_cast<const float4*>(xr + c4 * 4);
        float e0 = q.x - xv.x, e1 = q.y - xv.y, e2 = q.z - xv.z, e3 = q.w - xv.w;
        lsum = fmaf(e0, e0, lsum);
        lsum = fmaf(e1, e1, lsum);
        lsum = fmaf(e2, e2, lsum);
        lsum = fmaf(e3, e3, lsum);
        *reinterpret_cast<float4*>(orow + c4 * 4) = q;
    }
    // block reduce lsum
    #pragma unroll
    for (int off = 16; off > 0; off >>= 1)
        lsum += __shfl_down_sync(0xffffffffu, lsum, off);
    __shared__ float wsum[8];
    int wid = tid >> 5, lane = tid & 31;
    if (lane == 0) wsum[wid] = lsum;
    __syncthreads();
    if (tid == 0) {
        float s = 0.f;
        #pragma unroll
        for (int w = 0; w < 8; w++) s += wsum[w];
        atomicAdd(&g_loss, s);
    }
}

// -------- finalize: loss scalar + perplexity --------
__global__ void vq_finalize(float* __restrict__ out) {
    int tid = threadIdx.x;       // 1024 threads, one per code
    float c = (float)g_counts[tid];
    float p = c * (1.0f / (float)NROWS);
    float term = -p * logf(p + 1e-10f);   // p==0 -> -0 * log(1e-10) = 0
    #pragma unroll
    for (int off = 16; off > 0; off >>= 1)
        term += __shfl_down_sync(0xffffffffu, term, off);
    __shared__ float ws[32];
    int wid = tid >> 5, lane = tid & 31;
    if (lane == 0) ws[wid] = term;
    __syncthreads();
    if (tid < 32) {
        float v = ws[tid];
        #pragma unroll
        for (int off = 16; off > 0; off >>= 1)
            v += __shfl_down_sync(0xffffffffu, v, off);
        if (tid == 0) {
            out[NQ]     = g_loss * (1.25f / (float)NQ);
            out[NQ + 1] = expf(v);
        }
    }
}

extern "C" void kernel_launch(void* const* d_in, const int* in_sizes, int n_in,
                              void* d_out, int out_size) {
    const float* x = (const float*)d_in[0];   // [65536, 64]
    const float* E = (const float*)d_in[1];   // [64, 1024]
    float* out = (float*)d_out;

    const int smemBytes = (BM * ASTRIDE + 64 * BN + BN + BM + BM) * 4;  // 69120
    cudaFuncSetAttribute(vq_main, cudaFuncAttributeMaxDynamicSharedMemorySize, smemBytes);

    vq_prep<<<4, 256>>>(E);
    vq_main<<<NROWS / BM, 256, smemBytes>>>(x, E, out);
    vq_finalize<<<1, 1024>>>(out);
}

// round 6
// speedup vs baseline: 1.1019x; 1.1019x over previous
#include <cuda_runtime.h>
#include <stdint.h>
#include <math.h>

// VectorQuantizer: x [65536, 64] f32, embeddings [64, 1024] f32.
// d_out (f32): quantized[4194304], loss, perplexity, indices[65536] (as float)

#define NROWS 65536
#define DD    64
#define KC    1024
#define BM    128
#define BN    256          // codes per chunk
#define NCH   (KC / BN)    // 4
#define RS    129          // Ast stride (padded, conflict-free)
#define NQ    (NROWS * DD)

// -------- device scratch --------
__device__ float g_ET[KC * DD];
__device__ float g_enorm[KC];
__device__ int   g_counts[KC];
__device__ float g_loss;

typedef unsigned long long u64;
typedef unsigned int u32;

__device__ __forceinline__ u64 pack_dup(float a) {
    u64 r; asm("mov.b64 %0, {%1, %1};" : "=l"(r) : "f"(a)); return r;
}
__device__ __forceinline__ void fma2(u64 &d, u64 a, u64 b) {
    asm("fma.rn.f32x2 %0, %1, %2, %3;" : "=l"(d) : "l"(a), "l"(b), "l"(d));
}
__device__ __forceinline__ float2 unpack2(u64 v) {
    float2 f; asm("mov.b64 {%0, %1}, %2;" : "=f"(f.x), "=f"(f.y) : "l"(v)); return f;
}
__device__ __forceinline__ void cpa16(u32 saddr, const float* g) {
    asm volatile("cp.async.cg.shared.global [%0], [%1], 16;" :: "r"(saddr), "l"(g));
}
__device__ __forceinline__ void cpa_commit() {
    asm volatile("cp.async.commit_group;");
}
__device__ __forceinline__ void cpa_wait0() {
    asm volatile("cp.async.wait_group 0;");
}

// -------- prep: transpose E -> g_ET, zero scratch --------
__global__ void vq_prep(const float* __restrict__ E) {
    int b = blockIdx.x, tid = threadIdx.x;
    if (b < 4) { g_counts[b * 256 + tid] = 0; if (b == 0 && tid == 0) g_loss = 0.f; }
    int d0 = b * 2;
    #pragma unroll
    for (int it = 0; it < 8; it++) {
        int g = tid + 256 * it;
        int d = d0 + (g >> 10), k = g & 1023;
        g_ET[k * DD + d] = E[d * KC + k];
    }
}

// e-norms (deterministic, same summation order as round-1 pass)
__global__ void vq_prep2() {
    int k = blockIdx.x * 128 + threadIdx.x;
    const float4* p = reinterpret_cast<const float4*>(g_ET + k * DD);
    float s = 0.f;
    #pragma unroll
    for (int i = 0; i < 16; i++) {
        float4 v = p[i];
        s = fmaf(v.x, v.x, s); s = fmaf(v.y, v.y, s);
        s = fmaf(v.z, v.z, s); s = fmaf(v.w, v.w, s);
    }
    g_enorm[k] = s;
}

// -------- main: GEMM + argmin + gather + loss + histogram --------
extern __shared__ float sm[];

__global__ __launch_bounds__(256) void vq_main(const float* __restrict__ x,
                                               const float* __restrict__ E,
                                               float* __restrict__ out) {
    float* Ast     = sm;                         // 64 * 129 = 8256 floats
    float* Bs      = sm + DD * RS;               // 2 * 64 * 256 = 32768 floats
    float* xnorm_s = Bs + 2 * DD * BN;           // 128
    int*   win     = (int*)(xnorm_s + BM);       // 128

    const int tid = threadIdx.x;
    const int tx = tid & 15;
    const int ty = tid >> 4;
    const int ty8 = ty * 8;
    const int blockRow = blockIdx.x * BM;

    const u32 bsAddr = (u32)__cvta_generic_to_shared(Bs);

    // ---- prefetch B chunk 0 into buffer 0 ----
    #pragma unroll
    for (int it = 0; it < 16; it++) {
        int g = tid + 256 * it;           // 4096 float4s
        int d = g >> 6, c4 = g & 63;
        cpa16(bsAddr + (d * BN + c4 * 4) * 4, E + d * KC + c4 * 4);
    }
    cpa_commit();

    // ---- load x tile transposed: Ast[kk][row] ----
    const float* xg = x + (size_t)blockRow * DD;
    #pragma unroll
    for (int it = 0; it < 8; it++) {
        int g = tid + 256 * it;
        int row = g >> 4, c4 = g & 15;
        float4 v = *reinterpret_cast<const float4*>(xg + row * DD + c4 * 4);
        Ast[(c4 * 4 + 0) * RS + row] = v.x;
        Ast[(c4 * 4 + 1) * RS + row] = v.y;
        Ast[(c4 * 4 + 2) * RS + row] = v.z;
        Ast[(c4 * 4 + 3) * RS + row] = v.w;
    }
    __syncthreads();

    // ---- row norms ----
    if (tid < BM) {
        float s = 0.f;
        #pragma unroll
        for (int kk = 0; kk < DD; kk++) {
            float v = Ast[kk * RS + tid];
            s = fmaf(v, v, s);
        }
        xnorm_s[tid] = s;
    }
    cpa_wait0();
    __syncthreads();

    float best[8];
    int   bidx[8];
    #pragma unroll
    for (int i = 0; i < 8; i++) { best[i] = 3.4e38f; bidx[i] = 0; }

    for (int ch = 0; ch < NCH; ch++) {
        float* cur = Bs + (ch & 1) * (DD * BN);
        // prefetch next chunk into other buffer
        if (ch < NCH - 1) {
            u32 nb = bsAddr + (u32)(((ch + 1) & 1) * (DD * BN) * 4);
            const float* Eg = E + (ch + 1) * BN;
            #pragma unroll
            for (int it = 0; it < 16; it++) {
                int g = tid + 256 * it;
                int d = g >> 6, c4 = g & 63;
                cpa16(nb + (d * BN + c4 * 4) * 4, Eg + d * KC + c4 * 4);
            }
            cpa_commit();
        }

        u64 acc[8][4][2];
        #pragma unroll
        for (int i = 0; i < 8; i++)
            #pragma unroll
            for (int j = 0; j < 4; j++) { acc[i][j][0] = 0ULL; acc[i][j][1] = 0ULL; }

        #pragma unroll 4
        for (int kk = 0; kk < DD; kk++) {
            ulonglong2 b[4];
            #pragma unroll
            for (int j = 0; j < 4; j++)
                b[j] = *reinterpret_cast<const ulonglong2*>(cur + kk * BN + j * 64 + tx * 4);
            #pragma unroll
            for (int i = 0; i < 8; i++) {
                u64 av = pack_dup(Ast[kk * RS + ty8 + i]);
                #pragma unroll
                for (int j = 0; j < 4; j++) {
                    fma2(acc[i][j][0], av, b[j].x);
                    fma2(acc[i][j][1], av, b[j].y);
                }
            }
        }

        // distances + running argmin (codes ascending within thread)
        float4 en[4];
        #pragma unroll
        for (int j = 0; j < 4; j++)
            en[j] = *reinterpret_cast<const float4*>(g_enorm + ch * BN + j * 64 + tx * 4);

        #pragma unroll
        for (int i = 0; i < 8; i++) {
            float xn = xnorm_s[ty8 + i];
            #pragma unroll
            for (int j = 0; j < 4; j++) {
                float2 d0 = unpack2(acc[i][j][0]);
                float2 d1 = unpack2(acc[i][j][1]);
                int base = ch * BN + j * 64 + tx * 4;
                float v0 = (xn - 2.f * d0.x) + en[j].x;
                float v1 = (xn - 2.f * d0.y) + en[j].y;
                float v2 = (xn - 2.f * d1.x) + en[j].z;
                float v3 = (xn - 2.f * d1.y) + en[j].w;
                if (v0 < best[i]) { best[i] = v0; bidx[i] = base; }
                if (v1 < best[i]) { best[i] = v1; bidx[i] = base + 1; }
                if (v2 < best[i]) { best[i] = v2; bidx[i] = base + 2; }
                if (v3 < best[i]) { best[i] = v3; bidx[i] = base + 3; }
            }
        }

        if (ch < NCH - 1) cpa_wait0();
        __syncthreads();
    }

    // ---- cross-thread argmin reduction (reuse Bs) ----
    float* redD = Bs;
    int*   redI = (int*)(Bs + BM * 16);
    #pragma unroll
    for (int i = 0; i < 8; i++) {
        int r = ty8 + i;
        redD[r * 16 + tx] = best[i];
        redI[r * 16 + tx] = bidx[i];
    }
    __syncthreads();

    if (tid < BM) {
        float bd = redD[tid * 16];
        int   bi = redI[tid * 16];
        #pragma unroll
        for (int t = 1; t < 16; t++) {
            float d = redD[tid * 16 + t];
            int   ix = redI[tid * 16 + t];
            if (d < bd || (d == bd && ix < bi)) { bd = d; bi = ix; }
        }
        win[tid] = bi;
        atomicAdd(&g_counts[bi], 1);
        out[(size_t)NQ + 2 + blockRow + tid] = (float)bi;
    }
    __syncthreads();

    // ---- gather quantized rows + loss partial (x re-read from gmem: L2-hot) ----
    int r    = tid >> 1;
    int half = tid & 1;
    int idx  = win[r];
    const float* qrow = g_ET + idx * DD + half * 32;
    const float* xr   = x + ((size_t)(blockRow + r)) * DD + half * 32;
    float* orow = out + ((size_t)(blockRow + r)) * DD + half * 32;
    float lsum = 0.f;
    #pragma unroll
    for (int c4 = 0; c4 < 8; c4++) {
        float4 q  = *reinterpret_cast<const float4*>(qrow + c4 * 4);
        float4 xv = *reinterpret_cast<const float4*>(xr + c4 * 4);
        float e0 = q.x - xv.x, e1 = q.y - xv.y, e2 = q.z - xv.z, e3 = q.w - xv.w;
        lsum = fmaf(e0, e0, lsum);
        lsum = fmaf(e1, e1, lsum);
        lsum = fmaf(e2, e2, lsum);
        lsum = fmaf(e3, e3, lsum);
        *reinterpret_cast<float4*>(orow + c4 * 4) = q;
    }
    #pragma unroll
    for (int off = 16; off > 0; off >>= 1)
        lsum += __shfl_down_sync(0xffffffffu, lsum, off);
    __shared__ float wsum[8];
    int wid = tid >> 5, lane = tid & 31;
    if (lane == 0) wsum[wid] = lsum;
    __syncthreads();
    if (tid == 0) {
        float s = 0.f;
        #pragma unroll
        for (int w = 0; w < 8; w++) s += wsum[w];
        atomicAdd(&g_loss, s);
    }
}

// -------- finalize --------
__global__ void vq_finalize(float* __restrict__ out) {
    int tid = threadIdx.x;
    float c = (float)g_counts[tid];
    float p = c * (1.0f / (float)NROWS);
    float term = -p * logf(p + 1e-10f);
    #pragma unroll
    for (int off = 16; off > 0; off >>= 1)
        term += __shfl_down_sync(0xffffffffu, term, off);
    __shared__ float ws[32];
    int wid = tid >> 5, lane = tid & 31;
    if (lane == 0) ws[wid] = term;
    __syncthreads();
    if (tid < 32) {
        float v = ws[tid];
        #pragma unroll
        for (int off = 16; off > 0; off >>= 1)
            v += __shfl_down_sync(0xffffffffu, v, off);
        if (tid == 0) {
            out[NQ]     = g_loss * (1.25f / (float)NQ);
            out[NQ + 1] = expf(v);
        }
    }
}

extern "C" void kernel_launch(void* const* d_in, const int* in_sizes, int n_in,
                              void* d_out, int out_size) {
    const float* x = (const float*)d_in[0];
    const float* E = (const float*)d_in[1];
    float* out = (float*)d_out;

    const int smemBytes = (DD * RS + 2 * DD * BN + BM + BM) * 4;  // 165,120 B
    cudaFuncSetAttribute(vq_main, cudaFuncAttributeMaxDynamicSharedMemorySize, smemBytes);

    vq_prep<<<32, 256>>>(E);
    vq_prep2<<<8, 128>>>();
    vq_main<<<NROWS / BM, 256, smemBytes>>>(x, E, out);
    vq_finalize<<<1, 1024>>>(out);
}